// round 5
// baseline (speedup 1.0000x reference)
#include <cuda_runtime.h>
#include <cuda_fp16.h>
#include <cstdint>

#define BATCH   2048
#define IN_DIM  512
#define OUT_DIM 512
#define SDIM    8
#define KDIM    4096
#define ROWLEN  513

#define BM 128
#define BN 64
#define BK 32
#define STAGES 4
#define NTH 256
#define KSTEPS (KDIM / BK)          // 128

// rows padded to 40 fp16 (80B): conflict-free ldmatrix phases
#define SROWB 80
#define A_BYTES (BM * SROWB)        // 10240
#define B_BYTES (BN * SROWB)        // 5120
#define STAGE_BYTES (A_BYTES + B_BYTES)           // 15360
#define OFF_B A_BYTES
#define OFF_BASIS (STAGES * STAGE_BYTES)          // 61440
#define OFF_BW (OFF_BASIS + BM * SDIM * 4)        // 65536
#define SMEM_TOTAL (OFF_BW + SDIM * BN * 4)       // 67584

// ---------------------------------------------------------------------------
__device__ __forceinline__ uint32_t smem_u32(const void* p) {
    uint32_t a;
    asm("{ .reg .u64 t; cvta.to.shared.u64 t, %1; cvt.u32.u64 %0, t; }"
        : "=r"(a) : "l"(p));
    return a;
}
__device__ __forceinline__ void cp16(uint32_t dst, const void* src) {
    asm volatile("cp.async.cg.shared.global [%0], [%1], 16;"
                 :: "r"(dst), "l"(src) : "memory");
}
#define CP_COMMIT() asm volatile("cp.async.commit_group;" ::: "memory")
#define CP_WAIT(n)  asm volatile("cp.async.wait_group %0;" :: "n"(n) : "memory")

__device__ __forceinline__ void ldm_x4(uint32_t* r, uint32_t addr) {
    asm volatile("ldmatrix.sync.aligned.m8n8.x4.shared.b16 {%0,%1,%2,%3}, [%4];"
                 : "=r"(r[0]), "=r"(r[1]), "=r"(r[2]), "=r"(r[3]) : "r"(addr));
}
__device__ __forceinline__ void mma_f16(float* d, const uint32_t* a, const uint32_t* b) {
    asm volatile(
        "mma.sync.aligned.m16n8k16.row.col.f32.f16.f16.f32 "
        "{%0,%1,%2,%3}, {%4,%5,%6,%7}, {%8,%9}, {%0,%1,%2,%3};"
        : "+f"(d[0]), "+f"(d[1]), "+f"(d[2]), "+f"(d[3])
        : "r"(a[0]), "r"(a[1]), "r"(a[2]), "r"(a[3]), "r"(b[0]), "r"(b[1]));
}

// ---------------------------------------------------------------------------
// Device scratch
// ---------------------------------------------------------------------------
__device__ float g_basis[BATCH * SDIM];
__device__ __align__(16) __half g_F[BATCH * IN_DIM];    // features fp16 (2 MB)
__device__ __align__(16) __half g_Wt[OUT_DIM * KDIM];   // Wt[o][s*512+i] = W[s][i][o]

// ---------------------------------------------------------------------------
// Prep 1: F fp16 + basis
// ---------------------------------------------------------------------------
__global__ void prep_f_kernel(const float* __restrict__ inputs) {
    const int b   = blockIdx.x;
    const int tid = threadIdx.x;
    const float* row = inputs + (size_t)b * ROWLEN;
    if (tid < SDIM) {
        float t  = __ldg(row);
        float t2 = t * t, t3 = t2 * t;
        float bs[SDIM];
        bs[0] = 1.0f; bs[1] = t; bs[2] = t2; bs[3] = t3;
        const float kn[4] = {0.2f, 0.4f, 0.6f, 0.8f};
#pragma unroll
        for (int j = 0; j < 4; ++j) {
            float u = fmaxf(t - kn[j], 0.0f);
            bs[4 + j] = u * u * u;
        }
        g_basis[b * SDIM + tid] = bs[tid];
    }
    const float* feat = row + 1;
    float x0 = __ldg(&feat[2 * tid]);
    float x1 = __ldg(&feat[2 * tid + 1]);
    __half2 h = __floats2half2_rn(x0, x1);
    ((uint32_t*)(g_F + (size_t)b * IN_DIM))[tid] = *(uint32_t*)&h;
}

// ---------------------------------------------------------------------------
// Prep 2: Wt[o][s*512+i] = W[s][i][o], fp16
// ---------------------------------------------------------------------------
__global__ void prep_w_kernel(const float* __restrict__ W) {
    __shared__ float t[64][33];
    const int s  = blockIdx.z;
    const int i0 = blockIdx.x * 64, o0 = blockIdx.y * 32;
    const int tx = threadIdx.x, ty = threadIdx.y;
    for (int r = ty; r < 64; r += 8)
        t[r][tx] = W[((size_t)s << 18) + (size_t)(i0 + r) * 512 + o0 + tx];
    __syncthreads();
    for (int r = ty; r < 32; r += 8) {
        __half2 h = __floats2half2_rn(t[2 * tx][r], t[2 * tx + 1][r]);
        *(uint32_t*)&g_Wt[(size_t)(o0 + r) * KDIM + s * 512 + i0 + 2 * tx] =
            *(uint32_t*)&h;
    }
}

// ---------------------------------------------------------------------------
// Main GEMM: acc_s accumulates F @ W_s over k; at each s boundary fold
// acc += basis[m,s] * acc_s. A operand = F (2 MB, L2-resident).
// CTA 128x64, 8 warps (4m x 2n), warp tile 32x32, BK=32, 4-stage cp.async.
// ---------------------------------------------------------------------------
__global__ __launch_bounds__(NTH, 1)
void vclinear_mma_kernel(const float* __restrict__ bwts, float* __restrict__ out) {
    extern __shared__ char smem[];
    const uint32_t sb = smem_u32(smem);
    const int tid  = threadIdx.x;
    const int wid  = tid >> 5;
    const int lane = tid & 31;
    const int block_n = blockIdx.x * BN;
    const int block_m = blockIdx.y * BM;

    float* sBasis = (float*)(smem + OFF_BASIS);
    float* sBw    = (float*)(smem + OFF_BW);
    for (int q = tid; q < BM * SDIM; q += NTH)
        sBasis[q] = g_basis[(block_m + (q >> 3)) * SDIM + (q & 7)];
    for (int q = tid; q < SDIM * BN; q += NTH)
        sBw[q] = bwts[(q >> 6) * OUT_DIM + block_n + (q & 63)];
    __syncthreads();   // sBasis read during mainloop folds

    // cp.async mapping (256 threads): A 512 chunks -> 2/thread; B 256 -> 1/thread
    const int c  = tid & 3;
    const int r0 = tid >> 2;               // 0..63

#define LOAD_STAGE(ks, buf) do {                                               \
    const uint32_t s0 = sb + (buf) * STAGE_BYTES;                              \
    const int i0 = ((ks) * BK) & (IN_DIM - 1);                                 \
    cp16(s0 + r0 * SROWB + c * 16,                                             \
         g_F + (size_t)(block_m + r0) * IN_DIM + i0 + c * 8);                  \
    cp16(s0 + (r0 + 64) * SROWB + c * 16,                                      \
         g_F + (size_t)(block_m + r0 + 64) * IN_DIM + i0 + c * 8);             \
    cp16(s0 + OFF_B + r0 * SROWB + c * 16,                                     \
         g_Wt + (size_t)(block_n + r0) * KDIM + (size_t)(ks) * BK + c * 8);    \
} while (0)

    // warp tiling: 4m x 2n, warp tile 32x32
    const int m0 = (wid & 3) * 32;
    const int n0 = (wid >> 2) * 32;
    const uint32_t aoff = (m0 + (lane & 15)) * SROWB + (lane >> 4) * 16;
    const uint32_t boff = (n0 + (lane & 7) + ((lane >> 4) << 3)) * SROWB
                        + ((lane >> 3) & 1) * 16;

    float acc[2][4][4];    // final (basis-folded)
    float accs[2][4][4];   // per-s partial
#pragma unroll
    for (int i = 0; i < 2; ++i)
#pragma unroll
        for (int j = 0; j < 4; ++j)
#pragma unroll
            for (int r = 0; r < 4; ++r) { acc[i][j][r] = 0.0f; accs[i][j][r] = 0.0f; }

#pragma unroll
    for (int st = 0; st < STAGES - 1; ++st) {
        LOAD_STAGE(st, st);
        CP_COMMIT();
    }

    for (int ks = 0; ks < KSTEPS; ++ks) {
        CP_WAIT(STAGES - 2);
        __syncthreads();

        const int nxt = ks + STAGES - 1;
        if (nxt < KSTEPS) LOAD_STAGE(nxt, nxt & (STAGES - 1));
        CP_COMMIT();

        const uint32_t s0 = sb + (ks & (STAGES - 1)) * STAGE_BYTES;
#pragma unroll
        for (int kk = 0; kk < BK; kk += 16) {
            uint32_t a[2][4], b[2][4];
            ldm_x4(a[0], s0 + aoff + kk * 2);
            ldm_x4(a[1], s0 + aoff + 16 * SROWB + kk * 2);
            ldm_x4(b[0], s0 + OFF_B + boff + kk * 2);
            ldm_x4(b[1], s0 + OFF_B + boff + 16 * SROWB + kk * 2);
#pragma unroll
            for (int ma = 0; ma < 2; ++ma)
#pragma unroll
                for (int na = 0; na < 4; ++na)
                    mma_f16(accs[ma][na], a[ma], &b[na >> 1][(na & 1) * 2]);
        }

        // s boundary: fold accs into acc with basis weight, reset accs
        if ((ks & 15) == 15) {
            const int s = ks >> 4;
#pragma unroll
            for (int ma = 0; ma < 2; ++ma) {
#pragma unroll
                for (int half = 0; half < 2; ++half) {
                    const int row = m0 + ma * 16 + (lane >> 2) + half * 8;
                    const float bsv = sBasis[row * SDIM + s];
#pragma unroll
                    for (int na = 0; na < 4; ++na) {
#pragma unroll
                        for (int j = 0; j < 2; ++j) {
                            acc[ma][na][half * 2 + j] =
                                fmaf(bsv, accs[ma][na][half * 2 + j],
                                     acc[ma][na][half * 2 + j]);
                            accs[ma][na][half * 2 + j] = 0.0f;
                        }
                    }
                }
            }
        }
    }

    // epilogue: add bias = basis @ b_wts
#pragma unroll
    for (int ma = 0; ma < 2; ++ma) {
        const int rbase = m0 + ma * 16 + (lane >> 2);
#pragma unroll
        for (int half = 0; half < 2; ++half) {
            const int row = rbase + half * 8;
            float bsv[SDIM];
#pragma unroll
            for (int s = 0; s < SDIM; ++s) bsv[s] = sBasis[row * SDIM + s];
#pragma unroll
            for (int na = 0; na < 4; ++na) {
                const int col = n0 + na * 8 + 2 * (lane & 3);
                float b0 = 0.0f, b1 = 0.0f;
#pragma unroll
                for (int s = 0; s < SDIM; ++s) {
                    b0 = fmaf(bsv[s], sBw[s * BN + col], b0);
                    b1 = fmaf(bsv[s], sBw[s * BN + col + 1], b1);
                }
                float2 v;
                v.x = acc[ma][na][half * 2 + 0] + b0;
                v.y = acc[ma][na][half * 2 + 1] + b1;
                *(float2*)&out[(size_t)(block_m + row) * OUT_DIM + block_n + col] = v;
            }
        }
    }
}

// ---------------------------------------------------------------------------
extern "C" void kernel_launch(void* const* d_in, const int* in_sizes, int n_in,
                              void* d_out, int out_size) {
    const float* inputs = (const float*)d_in[0];   // (2048, 513)
    const float* W      = (const float*)d_in[1];   // (8, 512*512)
    const float* bwts   = (const float*)d_in[2];   // (8, 512)
    float* out          = (float*)d_out;           // (2048, 512)

    cudaFuncSetAttribute(vclinear_mma_kernel,
                         cudaFuncAttributeMaxDynamicSharedMemorySize, SMEM_TOTAL);

    prep_f_kernel<<<BATCH, 256>>>(inputs);
    dim3 gw(8, 16, 8), bw(32, 8);
    prep_w_kernel<<<gw, bw>>>(W);

    dim3 grid(OUT_DIM / BN, BATCH / BM);   // (8, 16) = 128 CTAs
    vclinear_mma_kernel<<<grid, NTH, SMEM_TOTAL>>>(bwts, out);
}

// round 7
// speedup vs baseline: 1.2569x; 1.2569x over previous
#include <cuda_runtime.h>
#include <cuda_fp16.h>
#include <cstdint>

#define BATCH   2048
#define IN_DIM  512
#define OUT_DIM 512
#define SDIM    8
#define KDIM    4096
#define ROWLEN  513

#define BM 128
#define BN 64
#define CHUNK 64                    // i-chunk width (BK)
#define NCHUNK (IN_DIM / CHUNK)     // 8
#define NITER (NCHUNK * SDIM)       // 64
#define NTH 128

// 64 fp16 = 128B data per row, pad to 144B (16B-aligned; 144/4=36 words ->
// 8-row ldmatrix phase hits word offsets {0,4,...,28}x4 = all 32 banks)
#define SROWB 144
#define A_BUF_BYTES (BM * SROWB)    // 18432, x2 buffers
#define B_BUF_BYTES (BN * SROWB)    // 9216,  x4 buffers
#define OFF_A 0
#define OFF_B (2 * A_BUF_BYTES)                    // 36864
#define OFF_BASIS (OFF_B + 4 * B_BUF_BYTES)        // 73728
#define OFF_BW (OFF_BASIS + BM * SDIM * 4)         // 77824
#define SMEM_TOTAL (OFF_BW + SDIM * BN * 4)        // 79872

// ---------------------------------------------------------------------------
__device__ __forceinline__ uint32_t smem_u32(const void* p) {
    uint32_t a;
    asm("{ .reg .u64 t; cvta.to.shared.u64 t, %1; cvt.u32.u64 %0, t; }"
        : "=r"(a) : "l"(p));
    return a;
}
__device__ __forceinline__ void cp16(uint32_t dst, const void* src) {
    asm volatile("cp.async.cg.shared.global [%0], [%1], 16;"
                 :: "r"(dst), "l"(src) : "memory");
}
#define CP_COMMIT() asm volatile("cp.async.commit_group;" ::: "memory")
#define CP_WAIT(n)  asm volatile("cp.async.wait_group %0;" :: "n"(n) : "memory")

__device__ __forceinline__ void ldm_x4(uint32_t* r, uint32_t addr) {
    asm volatile("ldmatrix.sync.aligned.m8n8.x4.shared.b16 {%0,%1,%2,%3}, [%4];"
                 : "=r"(r[0]), "=r"(r[1]), "=r"(r[2]), "=r"(r[3]) : "r"(addr));
}
__device__ __forceinline__ void mma_f16(float* d, const uint32_t* a, const uint32_t* b) {
    asm volatile(
        "mma.sync.aligned.m16n8k16.row.col.f32.f16.f16.f32 "
        "{%0,%1,%2,%3}, {%4,%5,%6,%7}, {%8,%9}, {%0,%1,%2,%3};"
        : "+f"(d[0]), "+f"(d[1]), "+f"(d[2]), "+f"(d[3])
        : "r"(a[0]), "r"(a[1]), "r"(a[2]), "r"(a[3]), "r"(b[0]), "r"(b[1]));
}

// ---------------------------------------------------------------------------
__device__ float g_basis[BATCH * SDIM];
__device__ __align__(16) __half g_F[BATCH * IN_DIM];    // features fp16 (2 MB)
__device__ __align__(16) __half g_Wt[OUT_DIM * KDIM];   // Wt[o][s*512+i] = W[s][i][o]

// ---------------------------------------------------------------------------
// Prep 1: F fp16 (grid-stride, 8-way ILP) + basis
// ---------------------------------------------------------------------------
__global__ void prep_f_kernel(const float* __restrict__ inputs) {
    const int t0 = blockIdx.x * 256 + threadIdx.x;     // 0..65535
#pragma unroll
    for (int j = 0; j < 8; ++j) {
        int g = t0 + j * 65536;                        // pair index
        int b = g >> 8, p = g & 255;
        const float* row = inputs + (size_t)b * ROWLEN;
        float x0 = __ldg(row + 1 + 2 * p);
        float x1 = __ldg(row + 2 + 2 * p);
        __half2 h = __floats2half2_rn(x0, x1);
        ((uint32_t*)g_F)[g] = *(uint32_t*)&h;
    }
    if (t0 < BATCH) {
        float t  = __ldg(&inputs[(size_t)t0 * ROWLEN]);
        float t2 = t * t, t3 = t2 * t;
        float* dst = &g_basis[t0 * SDIM];
        dst[0] = 1.0f; dst[1] = t; dst[2] = t2; dst[3] = t3;
        const float kn[4] = {0.2f, 0.4f, 0.6f, 0.8f};
#pragma unroll
        for (int j = 0; j < 4; ++j) {
            float u = fmaxf(t - kn[j], 0.0f);
            dst[4 + j] = u * u * u;
        }
    }
}

// ---------------------------------------------------------------------------
// Prep 2: Wt[o][s*512+i] = W[s][i][o], fp16
// ---------------------------------------------------------------------------
__global__ void prep_w_kernel(const float* __restrict__ W) {
    __shared__ float t[64][33];
    const int s  = blockIdx.z;
    const int i0 = blockIdx.x * 64, o0 = blockIdx.y * 32;
    const int tx = threadIdx.x, ty = threadIdx.y;
    for (int r = ty; r < 64; r += 8)
        t[r][tx] = W[((size_t)s << 18) + (size_t)(i0 + r) * 512 + o0 + tx];
    __syncthreads();
    for (int r = ty; r < 32; r += 8) {
        __half2 h = __floats2half2_rn(t[2 * tx][r], t[2 * tx + 1][r]);
        *(uint32_t*)&g_Wt[(size_t)(o0 + r) * KDIM + s * 512 + i0 + 2 * tx] =
            *(uint32_t*)&h;
    }
}

// ---------------------------------------------------------------------------
// GEMM: i-chunk outer, s inner; A tile loaded once per chunk; basis folded in
// registers at each (chunk,s) boundary. 4 warps, warp tile 64x32.
// ---------------------------------------------------------------------------
__global__ __launch_bounds__(NTH, 1)
void vclinear_mma_kernel(const float* __restrict__ bwts, float* __restrict__ out) {
    extern __shared__ char smem[];
    const uint32_t sb = smem_u32(smem);
    const int tid  = threadIdx.x;
    const int wid  = tid >> 5;
    const int lane = tid & 31;
    const int block_n = blockIdx.x * BN;
    const int block_m = blockIdx.y * BM;

    float* sBasis = (float*)(smem + OFF_BASIS);
    float* sBw    = (float*)(smem + OFF_BW);
    for (int q = tid; q < BM * SDIM; q += NTH)
        sBasis[q] = g_basis[(block_m + (q >> 3)) * SDIM + (q & 7)];
    for (int q = tid; q < SDIM * BN; q += NTH)
        sBw[q] = bwts[(q >> 6) * OUT_DIM + block_n + (q & 63)];
    __syncthreads();

    // cp.async mapping: 8 x 16B chunks per 128B row; 128 threads
    const int c  = tid & 7;                 // 16B chunk within row
    const int r0 = tid >> 3;                // 0..15

#define LOAD_B(iter, buf) do {                                                  \
    const uint32_t d = sb + OFF_B + (buf) * B_BUF_BYTES;                         \
    const size_t base = (size_t)block_n * KDIM                                   \
                      + ((iter) & 7) * 512 + ((iter) >> 3) * CHUNK + c * 8;      \
    _Pragma("unroll")                                                            \
    for (int j = 0; j < 4; ++j) {                                                \
        int row = r0 + j * 16;                                                   \
        cp16(d + row * SROWB + c * 16, g_Wt + base + (size_t)row * KDIM);        \
    }                                                                            \
} while (0)

#define LOAD_A(chunk) do {                                                      \
    const uint32_t d = sb + OFF_A + ((chunk) & 1) * A_BUF_BYTES;                 \
    const size_t base = (size_t)block_m * IN_DIM + (chunk) * CHUNK + c * 8;      \
    _Pragma("unroll")                                                            \
    for (int j = 0; j < 8; ++j) {                                                \
        int row = r0 + j * 16;                                                   \
        cp16(d + row * SROWB + c * 16, g_F + base + (size_t)row * IN_DIM);       \
    }                                                                            \
} while (0)

    // warp tiling: 2m x 2n, warp tile 64x32
    const int m0 = (wid >> 1) * 64;
    const int n0 = (wid & 1) * 32;
    const uint32_t aoff = (m0 + (lane & 15)) * SROWB + (lane >> 4) * 16;
    const uint32_t boff = (n0 + (lane & 7) + ((lane >> 4) << 3)) * SROWB
                        + ((lane >> 3) & 1) * 16;

    float acc[4][4][4];     // basis-folded output
    float accs[4][4][4];    // per-(chunk,s) partial
#pragma unroll
    for (int i = 0; i < 4; ++i)
#pragma unroll
        for (int j = 0; j < 4; ++j)
#pragma unroll
            for (int r = 0; r < 4; ++r) { acc[i][j][r] = 0.0f; accs[i][j][r] = 0.0f; }

    // prologue: G0 = {A chunk0, B iter0}; G1 = {B iter1}
    LOAD_A(0);
    LOAD_B(0, 0);
    CP_COMMIT();
    LOAD_B(1, 1);
    CP_COMMIT();

    for (int iter = 0; iter < NITER; ++iter) {
        CP_WAIT(1);
        __syncthreads();

        // prefetch iter+2 (exactly one commit per iter keeps accounting exact)
        const int nxt = iter + 2;
        if (nxt < NITER) {
            if ((nxt & 7) == 0) LOAD_A(nxt >> 3);
            LOAD_B(nxt, nxt & 3);
        }
        CP_COMMIT();

        const uint32_t aB = sb + OFF_A + ((iter >> 3) & 1) * A_BUF_BYTES;
        const uint32_t bB = sb + OFF_B + (iter & 3) * B_BUF_BYTES;
#pragma unroll
        for (int kk = 0; kk < 4; ++kk) {
            uint32_t a[4][4], b[2][4];
#pragma unroll
            for (int ma = 0; ma < 4; ++ma)
                ldm_x4(a[ma], aB + aoff + ma * 16 * SROWB + kk * 32);
#pragma unroll
            for (int nb = 0; nb < 2; ++nb)
                ldm_x4(b[nb], bB + boff + nb * 16 * SROWB + kk * 32);
#pragma unroll
            for (int ma = 0; ma < 4; ++ma)
#pragma unroll
                for (int na = 0; na < 4; ++na)
                    mma_f16(accs[ma][na], a[ma], &b[na >> 1][(na & 1) * 2]);
        }

        // fold accs into acc with basis[row][s]
        const int s = iter & 7;
#pragma unroll
        for (int ma = 0; ma < 4; ++ma) {
#pragma unroll
            for (int half = 0; half < 2; ++half) {
                const int row = m0 + ma * 16 + (lane >> 2) + half * 8;
                const float bsv = sBasis[row * SDIM + s];
#pragma unroll
                for (int na = 0; na < 4; ++na) {
#pragma unroll
                    for (int j = 0; j < 2; ++j) {
                        acc[ma][na][half * 2 + j] =
                            fmaf(bsv, accs[ma][na][half * 2 + j],
                                 acc[ma][na][half * 2 + j]);
                        accs[ma][na][half * 2 + j] = 0.0f;
                    }
                }
            }
        }
    }

    // epilogue: add bias = basis @ b_wts
#pragma unroll
    for (int ma = 0; ma < 4; ++ma) {
        const int rbase = m0 + ma * 16 + (lane >> 2);
#pragma unroll
        for (int half = 0; half < 2; ++half) {
            const int row = rbase + half * 8;
            float bsv[SDIM];
#pragma unroll
            for (int s = 0; s < SDIM; ++s) bsv[s] = sBasis[row * SDIM + s];
#pragma unroll
            for (int na = 0; na < 4; ++na) {
                const int col = n0 + na * 8 + 2 * (lane & 3);
                float b0 = 0.0f, b1 = 0.0f;
#pragma unroll
                for (int s = 0; s < SDIM; ++s) {
                    b0 = fmaf(bsv[s], sBw[s * BN + col], b0);
                    b1 = fmaf(bsv[s], sBw[s * BN + col + 1], b1);
                }
                float2 v;
                v.x = acc[ma][na][half * 2 + 0] + b0;
                v.y = acc[ma][na][half * 2 + 1] + b1;
                *(float2*)&out[(size_t)(block_m + row) * OUT_DIM + block_n + col] = v;
            }
        }
    }
}

// ---------------------------------------------------------------------------
extern "C" void kernel_launch(void* const* d_in, const int* in_sizes, int n_in,
                              void* d_out, int out_size) {
    const float* inputs = (const float*)d_in[0];   // (2048, 513)
    const float* W      = (const float*)d_in[1];   // (8, 512*512)
    const float* bwts   = (const float*)d_in[2];   // (8, 512)
    float* out          = (float*)d_out;           // (2048, 512)

    cudaFuncSetAttribute(vclinear_mma_kernel,
                         cudaFuncAttributeMaxDynamicSharedMemorySize, SMEM_TOTAL);

    prep_f_kernel<<<256, 256>>>(inputs);
    dim3 gw(8, 16, 8), bw(32, 8);
    prep_w_kernel<<<gw, bw>>>(W);

    dim3 grid(OUT_DIM / BN, BATCH / BM);   // (8, 16) = 128 CTAs
    vclinear_mma_kernel<<<grid, NTH, SMEM_TOTAL>>>(bwts, out);
}

// round 8
// speedup vs baseline: 1.3125x; 1.0442x over previous
#include <cuda_runtime.h>
#include <cuda_fp16.h>
#include <cstdint>

#define BATCH   2048
#define IN_DIM  512
#define OUT_DIM 512
#define SDIM    8
#define KDIM    4096
#define ROWLEN  513

#define BM 128
#define BN 64
#define CHUNK 64
#define NTH 256                      // 2 groups x 4 warps
#define GITER 32                     // iters per group (4 chunks x 8 s)

#define SROWB 144
#define A_BUF_BYTES (BM * SROWB)     // 18432; 2 per group -> 4
#define B_BUF_BYTES (BN * SROWB)     // 9216;  4 per group -> 8
#define OFF_A 0
#define OFF_B (4 * A_BUF_BYTES)                    // 73728
#define OFF_BASIS (OFF_B + 8 * B_BUF_BYTES)        // 147456
#define OFF_BW (OFF_BASIS + BM * SDIM * 4)         // 151552
#define SMEM_TOTAL (OFF_BW + SDIM * BN * 4)        // 153600
#define RED_STRIDE 66                // reduction staging stride (words)

// ---------------------------------------------------------------------------
__device__ __forceinline__ uint32_t smem_u32(const void* p) {
    uint32_t a;
    asm("{ .reg .u64 t; cvta.to.shared.u64 t, %1; cvt.u32.u64 %0, t; }"
        : "=r"(a) : "l"(p));
    return a;
}
__device__ __forceinline__ void cp16(uint32_t dst, const void* src) {
    asm volatile("cp.async.cg.shared.global [%0], [%1], 16;"
                 :: "r"(dst), "l"(src) : "memory");
}
#define CP_COMMIT() asm volatile("cp.async.commit_group;" ::: "memory")
#define CP_WAIT(n)  asm volatile("cp.async.wait_group %0;" :: "n"(n) : "memory")
#define BAR_GROUP(id) asm volatile("bar.sync %0, %1;" :: "r"(id), "r"(128) : "memory")

__device__ __forceinline__ void ldm_x4(uint32_t* r, uint32_t addr) {
    asm volatile("ldmatrix.sync.aligned.m8n8.x4.shared.b16 {%0,%1,%2,%3}, [%4];"
                 : "=r"(r[0]), "=r"(r[1]), "=r"(r[2]), "=r"(r[3]) : "r"(addr));
}
__device__ __forceinline__ void mma_f16(float* d, const uint32_t* a, const uint32_t* b) {
    asm volatile(
        "mma.sync.aligned.m16n8k16.row.col.f32.f16.f16.f32 "
        "{%0,%1,%2,%3}, {%4,%5,%6,%7}, {%8,%9}, {%0,%1,%2,%3};"
        : "+f"(d[0]), "+f"(d[1]), "+f"(d[2]), "+f"(d[3])
        : "r"(a[0]), "r"(a[1]), "r"(a[2]), "r"(a[3]), "r"(b[0]), "r"(b[1]));
}

// ---------------------------------------------------------------------------
__device__ float g_basis[BATCH * SDIM];
__device__ __align__(16) __half g_F[BATCH * IN_DIM];
__device__ __align__(16) __half g_Wt[OUT_DIM * KDIM];   // Wt[o][s*512+i]

// ---------------------------------------------------------------------------
// Merged prep: blocks 0..255 -> F fp16 + basis; blocks 256..1279 -> W transpose
// ---------------------------------------------------------------------------
__global__ void prep_kernel(const float* __restrict__ inputs,
                            const float* __restrict__ W) {
    __shared__ float t[64][33];
    const int bid = blockIdx.x;
    const int tid = threadIdx.x;
    if (bid < 256) {
        const int t0 = bid * 256 + tid;
#pragma unroll
        for (int j = 0; j < 8; ++j) {
            int g = t0 + j * 65536;
            int b = g >> 8, p = g & 255;
            const float* row = inputs + (size_t)b * ROWLEN;
            float x0 = __ldg(row + 1 + 2 * p);
            float x1 = __ldg(row + 2 + 2 * p);
            __half2 h = __floats2half2_rn(x0, x1);
            ((uint32_t*)g_F)[g] = *(uint32_t*)&h;
        }
        if (t0 < BATCH) {
            float tt = __ldg(&inputs[(size_t)t0 * ROWLEN]);
            float t2 = tt * tt, t3 = t2 * tt;
            float* dst = &g_basis[t0 * SDIM];
            dst[0] = 1.0f; dst[1] = tt; dst[2] = t2; dst[3] = t3;
            const float kn[4] = {0.2f, 0.4f, 0.6f, 0.8f};
#pragma unroll
            for (int j = 0; j < 4; ++j) {
                float u = fmaxf(tt - kn[j], 0.0f);
                dst[4 + j] = u * u * u;
            }
        }
    } else {
        const int wb = bid - 256;               // 0..1023
        const int s  = wb >> 7;
        const int i0 = (wb & 7) * 64;
        const int o0 = ((wb >> 3) & 15) * 32;
        const int tx = tid & 31, ty = tid >> 5;
        for (int r = ty; r < 64; r += 8)
            t[r][tx] = W[((size_t)s << 18) + (size_t)(i0 + r) * 512 + o0 + tx];
        __syncthreads();
        for (int r = ty; r < 32; r += 8) {
            __half2 h = __floats2half2_rn(t[2 * tx][r], t[2 * tx + 1][r]);
            *(uint32_t*)&g_Wt[(size_t)(o0 + r) * KDIM + s * 512 + i0 + 2 * tx] =
                *(uint32_t*)&h;
        }
    }
}

// ---------------------------------------------------------------------------
// GEMM: 2 k-split groups x 4 warps; group g does chunks [4g,4g+4), s inner,
// basis folded in registers; cross-group smem reduction at end.
// ---------------------------------------------------------------------------
__global__ __launch_bounds__(NTH, 1)
void vclinear_mma_kernel(const float* __restrict__ bwts, float* __restrict__ out) {
    extern __shared__ char smem[];
    const uint32_t sb = smem_u32(smem);
    const int tid  = threadIdx.x;
    const int g    = tid >> 7;              // group 0/1
    const int ltid = tid & 127;
    const int gwid = (tid >> 5) & 3;        // warp within group
    const int lane = tid & 31;
    const int block_n = blockIdx.x * BN;
    const int block_m = blockIdx.y * BM;

    float* sBasis = (float*)(smem + OFF_BASIS);
    float* sBw    = (float*)(smem + OFF_BW);
    for (int q = tid; q < BM * SDIM; q += NTH)
        sBasis[q] = g_basis[(block_m + (q >> 3)) * SDIM + (q & 7)];
    for (int q = tid; q < SDIM * BN; q += NTH)
        sBw[q] = bwts[(q >> 6) * OUT_DIM + block_n + (q & 63)];
    __syncthreads();

    const int c  = ltid & 7;
    const int r0 = ltid >> 3;               // 0..15

#define LOAD_B(it, buf) do {                                                     \
    const uint32_t d = sb + OFF_B + (g * 4 + (buf)) * B_BUF_BYTES;               \
    const size_t base = (size_t)block_n * KDIM + ((it) & 7) * 512               \
                      + (g * 4 + ((it) >> 3)) * CHUNK + c * 8;                   \
    _Pragma("unroll")                                                            \
    for (int j = 0; j < 4; ++j) {                                                \
        int row = r0 + j * 16;                                                   \
        cp16(d + row * SROWB + c * 16, g_Wt + base + (size_t)row * KDIM);        \
    }                                                                            \
} while (0)

#define LOAD_A(lc) do {                                                          \
    const uint32_t d = sb + OFF_A + (g * 2 + ((lc) & 1)) * A_BUF_BYTES;          \
    const size_t base = (size_t)block_m * IN_DIM + (g * 4 + (lc)) * CHUNK + c*8; \
    _Pragma("unroll")                                                            \
    for (int j = 0; j < 8; ++j) {                                                \
        int row = r0 + j * 16;                                                   \
        cp16(d + row * SROWB + c * 16, g_F + base + (size_t)row * IN_DIM);       \
    }                                                                            \
} while (0)

    // warp tiling within group: 2m x 2n, warp tile 64x32
    const int m0 = (gwid >> 1) * 64;
    const int n0 = (gwid & 1) * 32;
    const uint32_t aoff = (m0 + (lane & 15)) * SROWB + (lane >> 4) * 16;
    const uint32_t boff = (n0 + (lane & 7) + ((lane >> 4) << 3)) * SROWB
                        + ((lane >> 3) & 1) * 16;

    float acc[4][4][4];
    float accs[4][4][4];
#pragma unroll
    for (int i = 0; i < 4; ++i)
#pragma unroll
        for (int j = 0; j < 4; ++j)
#pragma unroll
            for (int r = 0; r < 4; ++r) { acc[i][j][r] = 0.0f; accs[i][j][r] = 0.0f; }

    // prologue (per group)
    LOAD_A(0);
    LOAD_B(0, 0);
    CP_COMMIT();
    LOAD_B(1, 1);
    CP_COMMIT();

    for (int it = 0; it < GITER; ++it) {
        CP_WAIT(1);
        BAR_GROUP(1 + g);

        const int nxt = it + 2;
        if (nxt < GITER) {
            if ((nxt & 7) == 0) LOAD_A(nxt >> 3);
            LOAD_B(nxt, nxt & 3);
        }
        CP_COMMIT();

        const uint32_t aB = sb + OFF_A + (g * 2 + ((it >> 3) & 1)) * A_BUF_BYTES;
        const uint32_t bB = sb + OFF_B + (g * 4 + (it & 3)) * B_BUF_BYTES;
#pragma unroll
        for (int kk = 0; kk < 4; ++kk) {
            uint32_t a[4][4], b[2][4];
#pragma unroll
            for (int ma = 0; ma < 4; ++ma)
                ldm_x4(a[ma], aB + aoff + ma * 16 * SROWB + kk * 32);
#pragma unroll
            for (int nb = 0; nb < 2; ++nb)
                ldm_x4(b[nb], bB + boff + nb * 16 * SROWB + kk * 32);
#pragma unroll
            for (int ma = 0; ma < 4; ++ma)
#pragma unroll
                for (int na = 0; na < 4; ++na)
                    mma_f16(accs[ma][na], a[ma], &b[na >> 1][(na & 1) * 2]);
        }

        const int s = it & 7;
#pragma unroll
        for (int ma = 0; ma < 4; ++ma) {
#pragma unroll
            for (int half = 0; half < 2; ++half) {
                const int row = m0 + ma * 16 + (lane >> 2) + half * 8;
                const float bsv = sBasis[row * SDIM + s];
#pragma unroll
                for (int na = 0; na < 4; ++na) {
#pragma unroll
                    for (int j = 0; j < 2; ++j) {
                        acc[ma][na][half * 2 + j] =
                            fmaf(bsv, accs[ma][na][half * 2 + j],
                                 acc[ma][na][half * 2 + j]);
                        accs[ma][na][half * 2 + j] = 0.0f;
                    }
                }
            }
        }
    }

    // cross-group reduction: g1 stages partials, g0 adds + bias + store
    float* red = (float*)(smem + OFF_A);    // 128*66*4 = 33792 B, buffers dead
    if (g == 1) {
#pragma unroll
        for (int ma = 0; ma < 4; ++ma)
#pragma unroll
            for (int half = 0; half < 2; ++half) {
                const int row = m0 + ma * 16 + (lane >> 2) + half * 8;
#pragma unroll
                for (int na = 0; na < 4; ++na) {
                    const int col = n0 + na * 8 + 2 * (lane & 3);
                    *(float2*)&red[row * RED_STRIDE + col] =
                        make_float2(acc[ma][na][half * 2], acc[ma][na][half * 2 + 1]);
                }
            }
    }
    __syncthreads();
    if (g == 0) {
#pragma unroll
        for (int ma = 0; ma < 4; ++ma) {
#pragma unroll
            for (int half = 0; half < 2; ++half) {
                const int row = m0 + ma * 16 + (lane >> 2) + half * 8;
                float bsv[SDIM];
#pragma unroll
                for (int s = 0; s < SDIM; ++s) bsv[s] = sBasis[row * SDIM + s];
#pragma unroll
                for (int na = 0; na < 4; ++na) {
                    const int col = n0 + na * 8 + 2 * (lane & 3);
                    float b0 = 0.0f, b1 = 0.0f;
#pragma unroll
                    for (int s = 0; s < SDIM; ++s) {
                        b0 = fmaf(bsv[s], sBw[s * BN + col], b0);
                        b1 = fmaf(bsv[s], sBw[s * BN + col + 1], b1);
                    }
                    float2 o = *(float2*)&red[row * RED_STRIDE + col];
                    float2 v;
                    v.x = acc[ma][na][half * 2 + 0] + o.x + b0;
                    v.y = acc[ma][na][half * 2 + 1] + o.y + b1;
                    *(float2*)&out[(size_t)(block_m + row) * OUT_DIM + block_n + col] = v;
                }
            }
        }
    }
}

// ---------------------------------------------------------------------------
extern "C" void kernel_launch(void* const* d_in, const int* in_sizes, int n_in,
                              void* d_out, int out_size) {
    const float* inputs = (const float*)d_in[0];
    const float* W      = (const float*)d_in[1];
    const float* bwts   = (const float*)d_in[2];
    float* out          = (float*)d_out;

    cudaFuncSetAttribute(vclinear_mma_kernel,
                         cudaFuncAttributeMaxDynamicSharedMemorySize, SMEM_TOTAL);

    prep_kernel<<<1280, 256>>>(inputs, W);

    dim3 grid(OUT_DIM / BN, BATCH / BM);   // 128 CTAs
    vclinear_mma_kernel<<<grid, NTH, SMEM_TOTAL>>>(bwts, out);
}

// round 9
// speedup vs baseline: 1.3733x; 1.0463x over previous
#include <cuda_runtime.h>
#include <cuda_fp16.h>
#include <cstdint>

#define BATCH   2048
#define IN_DIM  512
#define OUT_DIM 512
#define SDIM    8
#define KDIM    4096
#define ROWLEN  513

#define BM 128
#define BN 64
#define CHUNK 64
#define NTH 256                      // 2 groups x 4 warps
#define GITER 32                     // iters per group (4 chunks x 8 s)

#define SROWB 144
#define A_BUF_BYTES (BM * SROWB)     // 18432; 2 per group -> 4
#define B_BUF_BYTES (BN * SROWB)     // 9216;  4 per group -> 8
#define OFF_A 0
#define OFF_B (4 * A_BUF_BYTES)                    // 73728
#define OFF_BASIS (OFF_B + 8 * B_BUF_BYTES)        // 147456
#define OFF_BW (OFF_BASIS + BM * SDIM * 4)         // 151552
#define SMEM_TOTAL (OFF_BW + SDIM * BN * 4)        // 153600
#define RED_STRIDE 66

// ---------------------------------------------------------------------------
__device__ __forceinline__ uint32_t smem_u32(const void* p) {
    uint32_t a;
    asm("{ .reg .u64 t; cvta.to.shared.u64 t, %1; cvt.u32.u64 %0, t; }"
        : "=r"(a) : "l"(p));
    return a;
}
__device__ __forceinline__ void cp16(uint32_t dst, const void* src) {
    asm volatile("cp.async.cg.shared.global [%0], [%1], 16;"
                 :: "r"(dst), "l"(src) : "memory");
}
#define CP_COMMIT() asm volatile("cp.async.commit_group;" ::: "memory")
#define CP_WAIT(n)  asm volatile("cp.async.wait_group %0;" :: "n"(n) : "memory")
#define BAR_GROUP(id) asm volatile("bar.sync %0, %1;" :: "r"(id), "r"(128) : "memory")

__device__ __forceinline__ void ldm_x4(uint32_t* r, uint32_t addr) {
    asm volatile("ldmatrix.sync.aligned.m8n8.x4.shared.b16 {%0,%1,%2,%3}, [%4];"
                 : "=r"(r[0]), "=r"(r[1]), "=r"(r[2]), "=r"(r[3]) : "r"(addr));
}
__device__ __forceinline__ void mma_f16(float* d, const uint32_t* a, const uint32_t* b) {
    asm volatile(
        "mma.sync.aligned.m16n8k16.row.col.f32.f16.f16.f32 "
        "{%0,%1,%2,%3}, {%4,%5,%6,%7}, {%8,%9}, {%0,%1,%2,%3};"
        : "+f"(d[0]), "+f"(d[1]), "+f"(d[2]), "+f"(d[3])
        : "r"(a[0]), "r"(a[1]), "r"(a[2]), "r"(a[3]), "r"(b[0]), "r"(b[1]));
}

// ---------------------------------------------------------------------------
__device__ float g_basis[BATCH * SDIM];
__device__ __align__(16) __half g_F[BATCH * IN_DIM];
__device__ __align__(16) __half g_Wt[OUT_DIM * KDIM];   // Wt[o][s*512+i]

// ---------------------------------------------------------------------------
// Merged prep: blocks 0..255 -> F fp16 + basis; blocks 256..1279 -> W transpose
// ---------------------------------------------------------------------------
__global__ void prep_kernel(const float* __restrict__ inputs,
                            const float* __restrict__ W) {
    __shared__ float t[64][33];
    const int bid = blockIdx.x;
    const int tid = threadIdx.x;
    if (bid < 256) {
        const int t0 = bid * 256 + tid;
#pragma unroll
        for (int j = 0; j < 8; ++j) {
            int g = t0 + j * 65536;
            int b = g >> 8, p = g & 255;
            const float* row = inputs + (size_t)b * ROWLEN;
            float x0 = __ldg(row + 1 + 2 * p);
            float x1 = __ldg(row + 2 + 2 * p);
            __half2 h = __floats2half2_rn(x0, x1);
            ((uint32_t*)g_F)[g] = *(uint32_t*)&h;
        }
        if (t0 < BATCH) {
            float tt = __ldg(&inputs[(size_t)t0 * ROWLEN]);
            float t2 = tt * tt, t3 = t2 * tt;
            float* dst = &g_basis[t0 * SDIM];
            dst[0] = 1.0f; dst[1] = tt; dst[2] = t2; dst[3] = t3;
            const float kn[4] = {0.2f, 0.4f, 0.6f, 0.8f};
#pragma unroll
            for (int j = 0; j < 4; ++j) {
                float u = fmaxf(tt - kn[j], 0.0f);
                dst[4 + j] = u * u * u;
            }
        }
    } else {
        const int wb = bid - 256;
        const int s  = wb >> 7;
        const int i0 = (wb & 7) * 64;
        const int o0 = ((wb >> 3) & 15) * 32;
        const int tx = tid & 31, ty = tid >> 5;
        for (int r = ty; r < 64; r += 8)
            t[r][tx] = W[((size_t)s << 18) + (size_t)(i0 + r) * 512 + o0 + tx];
        __syncthreads();
        for (int r = ty; r < 32; r += 8) {
            __half2 h = __floats2half2_rn(t[2 * tx][r], t[2 * tx + 1][r]);
            *(uint32_t*)&g_Wt[(size_t)(o0 + r) * KDIM + s * 512 + i0 + 2 * tx] =
                *(uint32_t*)&h;
        }
    }
}

// ---------------------------------------------------------------------------
// GEMM: 2 k-split groups x 4 warps; register-double-buffered ldmatrix/HMMA,
// prefetch distance 3; basis folded in registers; cross-group reduction.
// ---------------------------------------------------------------------------
__global__ __launch_bounds__(NTH, 1)
void vclinear_mma_kernel(const float* __restrict__ bwts, float* __restrict__ out) {
    extern __shared__ char smem[];
    const uint32_t sb = smem_u32(smem);
    const int tid  = threadIdx.x;
    const int g    = tid >> 7;
    const int ltid = tid & 127;
    const int gwid = (tid >> 5) & 3;
    const int lane = tid & 31;
    const int block_n = blockIdx.x * BN;
    const int block_m = blockIdx.y * BM;

    float* sBasis = (float*)(smem + OFF_BASIS);
    float* sBw    = (float*)(smem + OFF_BW);
    for (int q = tid; q < BM * SDIM; q += NTH)
        sBasis[q] = g_basis[(block_m + (q >> 3)) * SDIM + (q & 7)];
    for (int q = tid; q < SDIM * BN; q += NTH)
        sBw[q] = bwts[(q >> 6) * OUT_DIM + block_n + (q & 63)];
    __syncthreads();

    const int c  = ltid & 7;
    const int r0 = ltid >> 3;

#define LOAD_B(it, buf) do {                                                     \
    const uint32_t d = sb + OFF_B + (g * 4 + (buf)) * B_BUF_BYTES;               \
    const size_t base = (size_t)block_n * KDIM + ((it) & 7) * 512               \
                      + (g * 4 + ((it) >> 3)) * CHUNK + c * 8;                   \
    _Pragma("unroll")                                                            \
    for (int j = 0; j < 4; ++j) {                                                \
        int row = r0 + j * 16;                                                   \
        cp16(d + row * SROWB + c * 16, g_Wt + base + (size_t)row * KDIM);        \
    }                                                                            \
} while (0)

#define LOAD_A(lc) do {                                                          \
    const uint32_t d = sb + OFF_A + (g * 2 + ((lc) & 1)) * A_BUF_BYTES;          \
    const size_t base = (size_t)block_m * IN_DIM + (g * 4 + (lc)) * CHUNK + c*8; \
    _Pragma("unroll")                                                            \
    for (int j = 0; j < 8; ++j) {                                                \
        int row = r0 + j * 16;                                                   \
        cp16(d + row * SROWB + c * 16, g_F + base + (size_t)row * IN_DIM);       \
    }                                                                            \
} while (0)

    const int m0 = (gwid >> 1) * 64;
    const int n0 = (gwid & 1) * 32;
    const uint32_t aoff = (m0 + (lane & 15)) * SROWB + (lane >> 4) * 16;
    const uint32_t boff = (n0 + (lane & 7) + ((lane >> 4) << 3)) * SROWB
                        + ((lane >> 3) & 1) * 16;

    float acc[4][4][4];
    float accs[4][4][4];
#pragma unroll
    for (int i = 0; i < 4; ++i)
#pragma unroll
        for (int j = 0; j < 4; ++j)
#pragma unroll
            for (int r = 0; r < 4; ++r) { acc[i][j][r] = 0.0f; accs[i][j][r] = 0.0f; }

    // prologue: distance-3 pipeline
    LOAD_A(0);
    LOAD_B(0, 0);
    CP_COMMIT();
    LOAD_B(1, 1);
    CP_COMMIT();
    LOAD_B(2, 2);
    CP_COMMIT();

#define LDM_SET(abuf, bbuf, kk) do {                                             \
    _Pragma("unroll")                                                            \
    for (int ma = 0; ma < 4; ++ma)                                               \
        ldm_x4(abuf[ma], aB + aoff + ma * 16 * SROWB + (kk) * 32);               \
    _Pragma("unroll")                                                            \
    for (int nb = 0; nb < 2; ++nb)                                               \
        ldm_x4(bbuf[nb], bB + boff + nb * 16 * SROWB + (kk) * 32);               \
} while (0)

#define MMA_SET(abuf, bbuf) do {                                                 \
    _Pragma("unroll")                                                            \
    for (int ma = 0; ma < 4; ++ma)                                               \
        _Pragma("unroll")                                                        \
        for (int na = 0; na < 4; ++na)                                           \
            mma_f16(accs[ma][na], abuf[ma], &bbuf[na >> 1][(na & 1) * 2]);       \
} while (0)

    for (int it = 0; it < GITER; ++it) {
        CP_WAIT(2);
        BAR_GROUP(1 + g);

        const int nxt = it + 3;
        if (nxt < GITER) {
            if ((nxt & 7) == 0) LOAD_A(nxt >> 3);
            LOAD_B(nxt, nxt & 3);
        }
        CP_COMMIT();

        const uint32_t aB = sb + OFF_A + (g * 2 + ((it >> 3) & 1)) * A_BUF_BYTES;
        const uint32_t bB = sb + OFF_B + (g * 4 + (it & 3)) * B_BUF_BYTES;

        // register double-buffered: LDSM(kk+1) overlaps MMA(kk)
        uint32_t a0[4][4], b0[2][4], a1[4][4], b1[2][4];
        LDM_SET(a0, b0, 0);
        LDM_SET(a1, b1, 1);
        MMA_SET(a0, b0);
        LDM_SET(a0, b0, 2);
        MMA_SET(a1, b1);
        LDM_SET(a1, b1, 3);
        MMA_SET(a0, b0);
        MMA_SET(a1, b1);

        // fold accs into acc with basis[row][s]
        const int s = it & 7;
#pragma unroll
        for (int ma = 0; ma < 4; ++ma) {
#pragma unroll
            for (int half = 0; half < 2; ++half) {
                const int row = m0 + ma * 16 + (lane >> 2) + half * 8;
                const float bsv = sBasis[row * SDIM + s];
#pragma unroll
                for (int na = 0; na < 4; ++na) {
#pragma unroll
                    for (int j = 0; j < 2; ++j) {
                        acc[ma][na][half * 2 + j] =
                            fmaf(bsv, accs[ma][na][half * 2 + j],
                                 acc[ma][na][half * 2 + j]);
                        accs[ma][na][half * 2 + j] = 0.0f;
                    }
                }
            }
        }
    }

    // cross-group reduction: g1 stages partials, g0 adds + bias + store
    float* red = (float*)(smem + OFF_A);
    if (g == 1) {
#pragma unroll
        for (int ma = 0; ma < 4; ++ma)
#pragma unroll
            for (int half = 0; half < 2; ++half) {
                const int row = m0 + ma * 16 + (lane >> 2) + half * 8;
#pragma unroll
                for (int na = 0; na < 4; ++na) {
                    const int col = n0 + na * 8 + 2 * (lane & 3);
                    *(float2*)&red[row * RED_STRIDE + col] =
                        make_float2(acc[ma][na][half * 2], acc[ma][na][half * 2 + 1]);
                }
            }
    }
    __syncthreads();
    if (g == 0) {
#pragma unroll
        for (int ma = 0; ma < 4; ++ma) {
#pragma unroll
            for (int half = 0; half < 2; ++half) {
                const int row = m0 + ma * 16 + (lane >> 2) + half * 8;
                float bsv[SDIM];
#pragma unroll
                for (int s = 0; s < SDIM; ++s) bsv[s] = sBasis[row * SDIM + s];
#pragma unroll
                for (int na = 0; na < 4; ++na) {
                    const int col = n0 + na * 8 + 2 * (lane & 3);
                    float b0r = 0.0f, b1r = 0.0f;
#pragma unroll
                    for (int s = 0; s < SDIM; ++s) {
                        b0r = fmaf(bsv[s], sBw[s * BN + col], b0r);
                        b1r = fmaf(bsv[s], sBw[s * BN + col + 1], b1r);
                    }
                    float2 o = *(float2*)&red[row * RED_STRIDE + col];
                    float2 v;
                    v.x = acc[ma][na][half * 2 + 0] + o.x + b0r;
                    v.y = acc[ma][na][half * 2 + 1] + o.y + b1r;
                    *(float2*)&out[(size_t)(block_m + row) * OUT_DIM + block_n + col] = v;
                }
            }
        }
    }
}

// ---------------------------------------------------------------------------
extern "C" void kernel_launch(void* const* d_in, const int* in_sizes, int n_in,
                              void* d_out, int out_size) {
    const float* inputs = (const float*)d_in[0];
    const float* W      = (const float*)d_in[1];
    const float* bwts   = (const float*)d_in[2];
    float* out          = (float*)d_out;

    cudaFuncSetAttribute(vclinear_mma_kernel,
                         cudaFuncAttributeMaxDynamicSharedMemorySize, SMEM_TOTAL);

    prep_kernel<<<1280, 256>>>(inputs, W);

    dim3 grid(OUT_DIM / BN, BATCH / BM);   // 128 CTAs
    vclinear_mma_kernel<<<grid, NTH, SMEM_TOTAL>>>(bwts, out);
}